// round 12
// baseline (speedup 1.0000x reference)
#include <cuda_runtime.h>
#include <stdint.h>

// -----------------------------------------------------------------------------
// Polynomial edge-energy + segment sum. (indices are int32)
//   per edge e: x = |pos[m0]-pos[m1]|, V = v0[t0,t1] + sum_p ks[p,t0,t1]*x^(p+1)
//   y[g] = segment sum over sorted mapping_batch
// R12: R11 occupancy plan with the warp-sync deadlock fixed — uniform per-block
//      iteration count + valid predicate so every thread executes every
//      __ballot/__shfl (no exited-lane UB). 2 edges/thread, 4 batched gathers,
//      int32 math, __launch_bounds__(256,8) -> 64 warps/SM.
// -----------------------------------------------------------------------------

#define MAX_NODES (1 << 17)   // 131072 >= N=100000
#define MAX_TT    1024        // >= T*T = 625
#define MAX_G     1024        // >= n_graphs = 512

__device__ float4 g_nodes[MAX_NODES];   // xyz + type-bits-as-float

// ---- prep: pack (pos, atom_type) into one float4 per node -------------------
__global__ void pack_nodes_kernel(const float* __restrict__ pos,
                                  const int* __restrict__ types,
                                  int N) {
    int i = blockIdx.x * blockDim.x + threadIdx.x;
    if (i < N) {
        float4 v;
        v.x = pos[3 * i + 0];
        v.y = pos[3 * i + 1];
        v.z = pos[3 * i + 2];
        v.w = __int_as_float(types[i]);   // bit reinterpret: free to decode
        g_nodes[i] = v;
    }
}

// ---- per-edge energy from two gathered node records --------------------------
__device__ __forceinline__ float pair_V(float4 n0, float4 n1,
                                        const float4* __restrict__ s_kk,
                                        const float* __restrict__ s_v0,
                                        int T) {
    float dx = n0.x - n1.x;
    float dy = n0.y - n1.y;
    float dz = n0.z - n1.z;
    float x2 = fmaf(dx, dx, fmaf(dy, dy, dz * dz));
    float x  = sqrtf(x2);
    int idx = __float_as_int(n0.w) * T + __float_as_int(n1.w);
    float4 k = s_kk[idx];
    float  v = s_v0[idx];
    // v0 + x*(k1 + x*(k2 + x*(k3 + x*k4)))
    return fmaf(x, fmaf(x, fmaf(x, fmaf(x, k.w, k.z), k.y), k.x), v);
}

// ---- main kernel -------------------------------------------------------------
__global__ void __launch_bounds__(256, 8)
poly_main_kernel(const int* __restrict__ map0,
                 const int* __restrict__ map1,
                 const int* __restrict__ batch,
                 const float* __restrict__ ks,
                 const float* __restrict__ v0g,
                 float* __restrict__ y,
                 int C,              // number of 2-edge chunks
                 int E,              // total edges (odd tail by block 0)
                 int T, int degs, int G) {
    __shared__ float4 s_kk[MAX_TT];
    __shared__ float  s_v0[MAX_TT];
    __shared__ float  s_y[MAX_G];

    const int TT = T * T;
    for (int i = threadIdx.x; i < TT; i += blockDim.x) {
        float4 k;
        k.x = ks[i];
        k.y = (degs > 1) ? ks[TT + i]     : 0.f;
        k.z = (degs > 2) ? ks[2 * TT + i] : 0.f;
        k.w = (degs > 3) ? ks[3 * TT + i] : 0.f;
        s_kk[i] = k;
        s_v0[i] = v0g[i];
    }
    for (int i = threadIdx.x; i < G; i += blockDim.x) s_y[i] = 0.f;
    __syncthreads();

    const int2* __restrict__ m0v = (const int2*)map0;
    const int2* __restrict__ m1v = (const int2*)map1;
    const int2* __restrict__ bv  = (const int2*)batch;

    // contiguous per-block chunk range, UNIFORM iteration count across block
    int cpb    = (C + (int)gridDim.x - 1) / (int)gridDim.x;
    int cstart = (int)blockIdx.x * cpb;
    int cend   = cstart + cpb;
    if (cend > C) cend = C;
    int range  = cend - cstart;
    int iters  = (range > 0) ? (range + 255) / 256 : 0;

    const int lane = threadIdx.x & 31;

    for (int it = 0; it < iters; ++it) {
        int  c     = cstart + it * 256 + (int)threadIdx.x;
        bool valid = (c < cend);
        float V0 = 0.f, V1 = 0.f;
        int2 bb = make_int2(0, 0);
        if (valid) {
            int2 ma = m0v[c];
            int2 mb = m1v[c];
            bb = bv[c];
            // batch 4 independent gathers before any dependent compute
            float4 n0 = g_nodes[ma.x];
            float4 n1 = g_nodes[mb.x];
            float4 n2 = g_nodes[ma.y];
            float4 n3 = g_nodes[mb.y];
            V0 = pair_V(n0, n1, s_kk, s_v0, T);
            V1 = pair_V(n2, n3, s_kk, s_v0, T);
        }
        // warp-uniform segment fast path (sorted batches -> ~always taken);
        // all 32 lanes always reach these syncs (valid folded into predicate)
        int bl = __shfl_sync(0xffffffffu, bb.x, 0);
        bool uni = valid && (bb.x == bl) && (bb.y == bl);
        if (__ballot_sync(0xffffffffu, uni) == 0xffffffffu) {
            float s = V0 + V1;
            #pragma unroll
            for (int o = 16; o > 0; o >>= 1)
                s += __shfl_xor_sync(0xffffffffu, s, o);
            if (lane == 0) atomicAdd(&s_y[bl], s);
        } else if (valid) {
            atomicAdd(&s_y[bb.x], V0);
            atomicAdd(&s_y[bb.y], V1);
        }
    }

    // odd trailing edge: block 0 only
    if (blockIdx.x == 0 && threadIdx.x == 0 && (E & 1)) {
        int e = E - 1;
        float4 a = g_nodes[map0[e]];
        float4 b = g_nodes[map1[e]];
        float V = pair_V(a, b, s_kk, s_v0, T);
        atomicAdd(&s_y[batch[e]], V);
    }

    __syncthreads();
    // each block spans few segments -> zero-guard keeps global atomics ~2/block
    for (int i = threadIdx.x; i < G; i += blockDim.x) {
        float v = s_y[i];
        if (v != 0.f) atomicAdd(&y[i], v);
    }
}

// ---- launch ------------------------------------------------------------------
extern "C" void kernel_launch(void* const* d_in, const int* in_sizes, int n_in,
                              void* d_out, int out_size) {
    const float* pos     = (const float*)d_in[0];  // (N,3)  f32
    const float* ks      = (const float*)d_in[1];  // (DEGS,T,T) f32
    const float* v0      = (const float*)d_in[2];  // (T,T) f32
    const int*   mapping = (const int*)d_in[3];    // (2,E) int32
    const int*   types   = (const int*)d_in[4];    // (N,)  int32
    const int*   mbatch  = (const int*)d_in[5];    // (E,)  int32, sorted
    float* y = (float*)d_out;                      // (G,)  f32

    const int N  = in_sizes[0] / 3;
    const int TT = in_sizes[2];           // T*T
    int T = 1;
    while ((T + 1) * (T + 1) <= TT) ++T;  // integer sqrt
    const int degs = in_sizes[1] / TT;
    const int E = in_sizes[5];
    const int G = out_size;

    const int* map0 = mapping;
    const int* map1 = mapping + E;
    const int C = E >> 1;                 // 2 edges per chunk

    cudaMemsetAsync(d_out, 0, (size_t)out_size * sizeof(float), 0);

    int prep_blocks = (N + 255) / 256;
    pack_nodes_kernel<<<prep_blocks, 256>>>(pos, types, N);

    // one full wave at 8 CTAs/SM (<=32 regs forced by launch bounds)
    int blocks = 148 * 8;
    poly_main_kernel<<<blocks, 256>>>(map0, map1, mbatch, ks, v0, y,
                                      C, E, T, degs, G);
}

// round 13
// speedup vs baseline: 1.3296x; 1.3296x over previous
#include <cuda_runtime.h>
#include <stdint.h>

// -----------------------------------------------------------------------------
// Polynomial edge-energy + segment sum. (indices are int32)
//   per edge e: x = |pos[m0]-pos[m1]|, V = v0[t0,t1] + sum_p ks[p,t0,t1]*x^(p+1)
//   y[g] = segment sum over sorted mapping_batch
// R13: break the per-warp serial chain (streams -> gathers -> compute) by
//      prefetching next iteration's stream loads into registers. 4 edges/thread
//      (8 batched gathers), int32 math, <=51 regs, ~5-iteration blocks so CLC
//      wave scheduling absorbs block-finish spread. No hot-loop barriers.
// -----------------------------------------------------------------------------

#define MAX_TT 1024        // >= T*T = 625
#define MAX_G  1024        // >= n_graphs = 512

__device__ float4 g_nodes[1 << 17];   // 131072 >= N; xyz + type-bits-as-float

// ---- prep: pack (pos, atom_type) into one float4 per node -------------------
__global__ void pack_nodes_kernel(const float* __restrict__ pos,
                                  const int* __restrict__ types,
                                  int N) {
    int i = blockIdx.x * blockDim.x + threadIdx.x;
    if (i < N) {
        float4 v;
        v.x = pos[3 * i + 0];
        v.y = pos[3 * i + 1];
        v.z = pos[3 * i + 2];
        v.w = __int_as_float(types[i]);   // bit reinterpret: free to decode
        g_nodes[i] = v;
    }
}

// ---- per-edge energy from two gathered node records --------------------------
__device__ __forceinline__ float pair_V(float4 n0, float4 n1,
                                        const float4* __restrict__ s_kk,
                                        const float* __restrict__ s_v0,
                                        int T) {
    float dx = n0.x - n1.x;
    float dy = n0.y - n1.y;
    float dz = n0.z - n1.z;
    float x2 = fmaf(dx, dx, fmaf(dy, dy, dz * dz));
    float x  = sqrtf(x2);
    int idx = __float_as_int(n0.w) * T + __float_as_int(n1.w);
    float4 k = s_kk[idx];
    float  v = s_v0[idx];
    // v0 + x*(k1 + x*(k2 + x*(k3 + x*k4)))
    return fmaf(x, fmaf(x, fmaf(x, fmaf(x, k.w, k.z), k.y), k.x), v);
}

// ---- main kernel -------------------------------------------------------------
__global__ void __launch_bounds__(256, 5)
poly_main_kernel(const int* __restrict__ map0,
                 const int* __restrict__ map1,
                 const int* __restrict__ batch,
                 const float* __restrict__ ks,
                 const float* __restrict__ v0g,
                 float* __restrict__ y,
                 int C,              // number of 4-edge chunks
                 int E,              // total edges (tail by block 0)
                 int T, int degs, int G) {
    __shared__ float4 s_kk[MAX_TT];
    __shared__ float  s_v0[MAX_TT];
    __shared__ float  s_y[MAX_G];

    const int TT = T * T;
    for (int i = threadIdx.x; i < TT; i += blockDim.x) {
        float4 k;
        k.x = ks[i];
        k.y = (degs > 1) ? ks[TT + i]     : 0.f;
        k.z = (degs > 2) ? ks[2 * TT + i] : 0.f;
        k.w = (degs > 3) ? ks[3 * TT + i] : 0.f;
        s_kk[i] = k;
        s_v0[i] = v0g[i];
    }
    for (int i = threadIdx.x; i < G; i += blockDim.x) s_y[i] = 0.f;
    __syncthreads();

    const int4* __restrict__ m0v = (const int4*)map0;
    const int4* __restrict__ m1v = (const int4*)map1;
    const int4* __restrict__ bv  = (const int4*)batch;

    // contiguous per-block chunk range, UNIFORM iteration count in block
    int cpb    = (C + (int)gridDim.x - 1) / (int)gridDim.x;
    int cstart = (int)blockIdx.x * cpb;
    int cend   = cstart + cpb;
    if (cend > C) cend = C;
    int range  = cend - cstart;
    int iters  = (range > 0) ? (range + 255) / 256 : 0;

    const int lane = threadIdx.x & 31;

    // prologue: prefetch iteration 0's stream data
    int4 ma, mb, bb;
    {
        int c = cstart + (int)threadIdx.x;
        if (c < cend) { ma = m0v[c]; mb = m1v[c]; bb = bv[c]; }
    }

    for (int it = 0; it < iters; ++it) {
        int  c     = cstart + it * 256 + (int)threadIdx.x;
        bool valid = (c < cend);
        int  cn    = c + 256;
        bool vnext = (cn < cend);

        // prefetch next iteration's streams (independent of current work)
        int4 man, mbn, bbn;
        if (vnext) { man = m0v[cn]; mbn = m1v[cn]; bbn = bv[cn]; }

        float V0 = 0.f, V1 = 0.f, V2 = 0.f, V3 = 0.f;
        if (valid) {
            // 8 independent gathers from already-resident indices
            float4 n0 = g_nodes[ma.x];
            float4 n1 = g_nodes[mb.x];
            float4 n2 = g_nodes[ma.y];
            float4 n3 = g_nodes[mb.y];
            float4 n4 = g_nodes[ma.z];
            float4 n5 = g_nodes[mb.z];
            float4 n6 = g_nodes[ma.w];
            float4 n7 = g_nodes[mb.w];
            V0 = pair_V(n0, n1, s_kk, s_v0, T);
            V1 = pair_V(n2, n3, s_kk, s_v0, T);
            V2 = pair_V(n4, n5, s_kk, s_v0, T);
            V3 = pair_V(n6, n7, s_kk, s_v0, T);
        }

        // warp-uniform segment fast path (sorted batches); iters is uniform in
        // the block so every lane reaches every sync (valid folded into preds)
        int bl = __shfl_sync(0xffffffffu, bb.x, 0);
        bool uni = valid && (bb.x == bl) && (bb.y == bl) &&
                            (bb.z == bl) && (bb.w == bl);
        if (__ballot_sync(0xffffffffu, uni) == 0xffffffffu) {
            float s = (V0 + V1) + (V2 + V3);
            #pragma unroll
            for (int o = 16; o > 0; o >>= 1)
                s += __shfl_xor_sync(0xffffffffu, s, o);
            if (lane == 0) atomicAdd(&s_y[bl], s);
        } else if (valid) {
            atomicAdd(&s_y[bb.x], V0);
            atomicAdd(&s_y[bb.y], V1);
            atomicAdd(&s_y[bb.z], V2);
            atomicAdd(&s_y[bb.w], V3);
        }

        ma = man; mb = mbn; bb = bbn;   // rotate pipeline
    }

    // trailing edges (E % 4 != 0): block 0 only
    if (blockIdx.x == 0 && threadIdx.x == 0) {
        for (int e = C * 4; e < E; ++e) {
            float4 a = g_nodes[map0[e]];
            float4 b = g_nodes[map1[e]];
            float V = pair_V(a, b, s_kk, s_v0, T);
            atomicAdd(&s_y[batch[e]], V);
        }
    }

    __syncthreads();
    // each block spans few segments -> zero-guard keeps global atomics ~2/block
    for (int i = threadIdx.x; i < G; i += blockDim.x) {
        float v = s_y[i];
        if (v != 0.f) atomicAdd(&y[i], v);
    }
}

// ---- launch ------------------------------------------------------------------
extern "C" void kernel_launch(void* const* d_in, const int* in_sizes, int n_in,
                              void* d_out, int out_size) {
    const float* pos     = (const float*)d_in[0];  // (N,3)  f32
    const float* ks      = (const float*)d_in[1];  // (DEGS,T,T) f32
    const float* v0      = (const float*)d_in[2];  // (T,T) f32
    const int*   mapping = (const int*)d_in[3];    // (2,E) int32
    const int*   types   = (const int*)d_in[4];    // (N,)  int32
    const int*   mbatch  = (const int*)d_in[5];    // (E,)  int32, sorted
    float* y = (float*)d_out;                      // (G,)  f32

    const int N  = in_sizes[0] / 3;
    const int TT = in_sizes[2];           // T*T
    int T = 1;
    while ((T + 1) * (T + 1) <= TT) ++T;  // integer sqrt
    const int degs = in_sizes[1] / TT;
    const int E = in_sizes[5];
    const int G = out_size;

    const int* map0 = mapping;
    const int* map1 = mapping + E;
    const int C = E >> 2;                 // 4 edges per chunk

    cudaMemsetAsync(d_out, 0, (size_t)out_size * sizeof(float), 0);

    int prep_blocks = (N + 255) / 256;
    pack_nodes_kernel<<<prep_blocks, 256>>>(pos, types, N);

    // many short blocks (~5 iterations each): CLC waves absorb finish spread
    int blocks = 2960;
    poly_main_kernel<<<blocks, 256>>>(map0, map1, mbatch, ks, v0, y,
                                      C, E, T, degs, G);
}

// round 14
// speedup vs baseline: 1.4178x; 1.0664x over previous
#include <cuda_runtime.h>
#include <stdint.h>

// -----------------------------------------------------------------------------
// Polynomial edge-energy + segment sum. (indices are int32)
//   per edge e: x = |pos[m0]-pos[m1]|, V = v0[t0,t1] + sum_p ks[p,t0,t1]*x^(p+1)
//   y[g] = segment sum over sorted mapping_batch
// R14: kernel is at the divergent-gather l1tex replay floor; remove everything
//      else from the hot loop. mapping_batch is SORTED -> precompute segment
//      boundaries (513 ints) once; per-lane (seg,bound,acc) in registers.
//      Hot loop = 2 stream loads + 8 gathers + Horner + 1 compare. No warp
//      collectives, no hot-loop atomics, no batch stream (saves 32MB DRAM).
// -----------------------------------------------------------------------------

#define MAX_TT 1024        // >= T*T = 625
#define MAX_G  1024        // >= n_graphs = 512

__device__ float4 g_nodes[1 << 17];     // 131072 >= N; xyz + type-bits-as-float
__device__ int    g_seg_bnd[MAX_G + 1]; // segment boundaries: lb(batch, g)

// ---- prep 1: pack (pos, atom_type) into one float4 per node -----------------
__global__ void pack_nodes_kernel(const float* __restrict__ pos,
                                  const int* __restrict__ types,
                                  int N) {
    int i = blockIdx.x * blockDim.x + threadIdx.x;
    if (i < N) {
        float4 v;
        v.x = pos[3 * i + 0];
        v.y = pos[3 * i + 1];
        v.z = pos[3 * i + 2];
        v.w = __int_as_float(types[i]);   // bit reinterpret: free to decode
        g_nodes[i] = v;
    }
}

// ---- prep 2: segment boundaries via binary search (sorted batch) ------------
__global__ void seg_bounds_kernel(const int* __restrict__ batch, int E, int G) {
    int g = blockIdx.x * blockDim.x + threadIdx.x;
    if (g > G) return;
    int lo = 0, hi = E;                  // first idx with batch[idx] >= g
    while (lo < hi) {
        int mid = (lo + hi) >> 1;
        if (batch[mid] < g) lo = mid + 1; else hi = mid;
    }
    g_seg_bnd[g] = lo;
}

// ---- per-edge energy from two gathered node records --------------------------
__device__ __forceinline__ float pair_V(float4 n0, float4 n1,
                                        const float4* __restrict__ s_kk,
                                        const float* __restrict__ s_v0,
                                        int T) {
    float dx = n0.x - n1.x;
    float dy = n0.y - n1.y;
    float dz = n0.z - n1.z;
    float x2 = fmaf(dx, dx, fmaf(dy, dy, dz * dz));
    float x  = sqrtf(x2);
    int idx = __float_as_int(n0.w) * T + __float_as_int(n1.w);
    float4 k = s_kk[idx];
    float  v = s_v0[idx];
    // v0 + x*(k1 + x*(k2 + x*(k3 + x*k4)))
    return fmaf(x, fmaf(x, fmaf(x, fmaf(x, k.w, k.z), k.y), k.x), v);
}

// ---- main kernel -------------------------------------------------------------
__global__ void __launch_bounds__(256, 6)
poly_main_kernel(const int* __restrict__ map0,
                 const int* __restrict__ map1,
                 const float* __restrict__ ks,
                 const float* __restrict__ v0g,
                 float* __restrict__ y,
                 int C,              // number of 4-edge chunks
                 int E,              // total edges (tail by block 0)
                 int T, int degs, int G) {
    __shared__ float4 s_kk[MAX_TT];
    __shared__ float  s_v0[MAX_TT];
    __shared__ float  s_y[MAX_G];
    __shared__ int    s_bnd[MAX_G + 1];

    const int TT = T * T;
    for (int i = threadIdx.x; i < TT; i += blockDim.x) {
        float4 k;
        k.x = ks[i];
        k.y = (degs > 1) ? ks[TT + i]     : 0.f;
        k.z = (degs > 2) ? ks[2 * TT + i] : 0.f;
        k.w = (degs > 3) ? ks[3 * TT + i] : 0.f;
        s_kk[i] = k;
        s_v0[i] = v0g[i];
    }
    for (int i = threadIdx.x; i < G; i += blockDim.x) s_y[i] = 0.f;
    for (int i = threadIdx.x; i <= G; i += blockDim.x) s_bnd[i] = g_seg_bnd[i];
    __syncthreads();

    const int4* __restrict__ m0v = (const int4*)map0;
    const int4* __restrict__ m1v = (const int4*)map1;

    // contiguous per-block chunk range (int32 math)
    int cpb    = (C + (int)gridDim.x - 1) / (int)gridDim.x;
    int cstart = (int)blockIdx.x * cpb + (int)threadIdx.x;
    int cend   = (int)blockIdx.x * cpb + cpb;
    if (cend > C) cend = C;

    // per-lane running segment state (no warp collectives needed in loop)
    int   seg = 0, nb = 0;
    float acc = 0.f;
    bool  has = (cstart < cend);
    if (has) {
        int e0 = 4 * cstart;
        int lo = 0, hi = G - 1;          // largest g with s_bnd[g] <= e0
        while (lo < hi) {
            int mid = (lo + hi + 1) >> 1;
            if (s_bnd[mid] <= e0) lo = mid; else hi = mid - 1;
        }
        seg = lo;
        nb  = s_bnd[seg + 1];
    }

    for (int c = cstart; c < cend; c += 256) {
        int4 ma = m0v[c];
        int4 mb = m1v[c];
        // 8 independent divergent gathers (the l1tex replay floor)
        float4 n0 = g_nodes[ma.x];
        float4 n1 = g_nodes[mb.x];
        float4 n2 = g_nodes[ma.y];
        float4 n3 = g_nodes[mb.y];
        float4 n4 = g_nodes[ma.z];
        float4 n5 = g_nodes[mb.z];
        float4 n6 = g_nodes[ma.w];
        float4 n7 = g_nodes[mb.w];

        float V0 = pair_V(n0, n1, s_kk, s_v0, T);
        float V1 = pair_V(n2, n3, s_kk, s_v0, T);
        float V2 = pair_V(n4, n5, s_kk, s_v0, T);
        float V3 = pair_V(n6, n7, s_kk, s_v0, T);

        int e3 = 4 * c + 3;
        if (e3 < nb) {
            acc += (V0 + V1) + (V2 + V3);   // fast path: whole chunk in segment
        } else {
            // segment crossing (rare: ~3 per lane per kernel)
            #pragma unroll
            for (int j = 0; j < 4; ++j) {
                int e = 4 * c + j;
                if (e >= nb) {
                    atomicAdd(&s_y[seg], acc);
                    acc = 0.f;
                    do { ++seg; nb = s_bnd[seg + 1]; } while (e >= nb);
                }
                acc += (j == 0) ? V0 : (j == 1) ? V1 : (j == 2) ? V2 : V3;
            }
        }
    }
    if (has) atomicAdd(&s_y[seg], acc);

    // trailing edges (E % 4 != 0): block 0 only
    if (blockIdx.x == 0 && threadIdx.x == 0) {
        for (int e = C * 4; e < E; ++e) {
            float4 a = g_nodes[map0[e]];
            float4 b = g_nodes[map1[e]];
            float V = pair_V(a, b, s_kk, s_v0, T);
            int lo = 0, hi = G - 1;
            while (lo < hi) {
                int mid = (lo + hi + 1) >> 1;
                if (s_bnd[mid] <= e) lo = mid; else hi = mid - 1;
            }
            atomicAdd(&s_y[lo], V);
        }
    }

    __syncthreads();
    // each block spans few segments -> zero-guard keeps global atomics ~2/block
    for (int i = threadIdx.x; i < G; i += blockDim.x) {
        float v = s_y[i];
        if (v != 0.f) atomicAdd(&y[i], v);
    }
}

// ---- launch ------------------------------------------------------------------
extern "C" void kernel_launch(void* const* d_in, const int* in_sizes, int n_in,
                              void* d_out, int out_size) {
    const float* pos     = (const float*)d_in[0];  // (N,3)  f32
    const float* ks      = (const float*)d_in[1];  // (DEGS,T,T) f32
    const float* v0      = (const float*)d_in[2];  // (T,T) f32
    const int*   mapping = (const int*)d_in[3];    // (2,E) int32
    const int*   types   = (const int*)d_in[4];    // (N,)  int32
    const int*   mbatch  = (const int*)d_in[5];    // (E,)  int32, sorted
    float* y = (float*)d_out;                      // (G,)  f32

    const int N  = in_sizes[0] / 3;
    const int TT = in_sizes[2];           // T*T
    int T = 1;
    while ((T + 1) * (T + 1) <= TT) ++T;  // integer sqrt
    const int degs = in_sizes[1] / TT;
    const int E = in_sizes[5];
    const int G = out_size;

    const int* map0 = mapping;
    const int* map1 = mapping + E;
    const int C = E >> 2;                 // 4 edges per chunk

    cudaMemsetAsync(d_out, 0, (size_t)out_size * sizeof(float), 0);

    int prep_blocks = (N + 255) / 256;
    pack_nodes_kernel<<<prep_blocks, 256>>>(pos, types, N);
    seg_bounds_kernel<<<(G + 256) / 256, 256>>>(mbatch, E, G);

    // one wave at 6 CTAs/SM (<=42 regs via launch bounds)
    int blocks = 148 * 6;
    poly_main_kernel<<<blocks, 256>>>(map0, map1, ks, v0, y,
                                      C, E, T, degs, G);
}